// round 12
// baseline (speedup 1.0000x reference)
#include <cuda_runtime.h>

// Problem constants
constexpr int NB = 32;    // batch
constexpr int NT = 1024;  // tokens (32x32)
constexpr int NF = 768;   // features
constexpr int NS = 32;    // splits per batch in pass C
constexpr int TOK_PER_BLK  = NT / NS;       // 32 tokens per kC block
constexpr int TOK_PER_WARP = TOK_PER_BLK/8; // 4 tokens per warp
constexpr int BLK_PER_BATCH_A = NT / 8;     // 128 kA blocks per batch

// Scratch (device globals — no allocations; counters self-reset per launch)
__device__ float4 g_meta[NB * NT];   // {rnorm, p1, tok.fw0, tok.fw1}
__device__ float  g_q[NB * NF];      // normalized argmax token per batch
__device__ float  g_d0[NB * NS];
__device__ float  g_d1[NB * NS];
__device__ float  g_u [NB * NS];
__device__ unsigned g_cntA[NB];
__device__ unsigned g_cntC;

// ---------------------------------------------------------------------------
// Kernel A: one warp per token. Computes ||tok||, tok.fc_w{0,1} (-> p1) and
// tok.fc_final_w{0,1} (pre-projections used by kC). Packs all four per-token
// scalars into one float4. Last-finishing block per batch does the argmax
// (first-max tiebreak, matches jnp.argmax) and writes q = tok[idx]*rnorm.
// ---------------------------------------------------------------------------
__global__ __launch_bounds__(256) void kA(const float* __restrict__ x,
                                          const float* __restrict__ fc_w,
                                          const float* __restrict__ fc_b,
                                          const float* __restrict__ fc_final_w) {
    const int warp = threadIdx.x >> 5;
    const int lane = threadIdx.x & 31;
    const int g = blockIdx.x * 8 + warp;          // global token id
    const int b = blockIdx.x / BLK_PER_BATCH_A;   // batch of this block

    __shared__ float ws[4 * NF];                  // 12 KB: fc_w0,1 + fcf_w0,1
    for (int i = threadIdx.x; i < 2 * NF; i += 256) ws[i] = fc_w[i];
    for (int i = threadIdx.x; i < 2 * NF; i += 256) ws[2 * NF + i] = fc_final_w[i];
    __syncthreads();
    const float4* w0 = reinterpret_cast<const float4*>(ws);
    const float4* w1 = reinterpret_cast<const float4*>(ws + NF);
    const float4* f0 = reinterpret_cast<const float4*>(ws + 2 * NF);
    const float4* f1 = reinterpret_cast<const float4*>(ws + 3 * NF);

    const float4* tok = reinterpret_cast<const float4*>(x + (size_t)g * NF);

    float nrm = 0.f, d0 = 0.f, d1 = 0.f, e0 = 0.f, e1 = 0.f;
#pragma unroll
    for (int i = 0; i < 6; i++) {
        float4 v = tok[lane + 32 * i];
        float4 a = w0[lane + 32 * i];
        float4 c = w1[lane + 32 * i];
        float4 p = f0[lane + 32 * i];
        float4 q = f1[lane + 32 * i];
        nrm += v.x * v.x + v.y * v.y + v.z * v.z + v.w * v.w;
        d0  += v.x * a.x + v.y * a.y + v.z * a.z + v.w * a.w;
        d1  += v.x * c.x + v.y * c.y + v.z * c.z + v.w * c.w;
        e0  += v.x * p.x + v.y * p.y + v.z * p.z + v.w * p.w;
        e1  += v.x * q.x + v.y * q.y + v.z * q.z + v.w * q.w;
    }
#pragma unroll
    for (int o = 16; o; o >>= 1) {
        nrm += __shfl_xor_sync(0xffffffffu, nrm, o);
        d0  += __shfl_xor_sync(0xffffffffu, d0, o);
        d1  += __shfl_xor_sync(0xffffffffu, d1, o);
        e0  += __shfl_xor_sync(0xffffffffu, e0, o);
        e1  += __shfl_xor_sync(0xffffffffu, e1, o);
    }
    if (lane == 0) {
        const float p1 = 1.f / (1.f + expf((d0 + fc_b[0]) - (d1 + fc_b[1])));
        g_meta[g] = make_float4(rsqrtf(nrm), p1, e0, e1);
    }
    __syncthreads();

    // Single release fence per block (syncthreads orders all block writes
    // before thread 0's gpu-scope fence + atomic).
    __shared__ unsigned s_last;
    if (threadIdx.x == 0) {
        __threadfence();
        s_last = atomicAdd(&g_cntA[b], 1u);
    }
    __syncthreads();
    if (s_last != BLK_PER_BATCH_A - 1) return;
    __threadfence();  // acquire: see all blocks' meta writes

    // argmax over 1024 p1 values, 256 threads x 4 candidates.
    // Comparator (v>best)||(v==best && i<besti) => global first-max.
    float bestv = -1.f; int besti = 0;
#pragma unroll
    for (int k = 0; k < 4; k++) {
        const int t = threadIdx.x + 256 * k;
        const float v = g_meta[b * NT + t].y;
        if (v > bestv || (v == bestv && t < besti)) { bestv = v; besti = t; }
    }
#pragma unroll
    for (int o = 16; o; o >>= 1) {
        float v2 = __shfl_xor_sync(0xffffffffu, bestv, o);
        int   i2 = __shfl_xor_sync(0xffffffffu, besti, o);
        if (v2 > bestv || (v2 == bestv && i2 < besti)) { bestv = v2; besti = i2; }
    }
    __shared__ float swv[8];
    __shared__ int   swi[8];
    if (lane == 0) { swv[warp] = bestv; swi[warp] = besti; }
    __syncthreads();
    __shared__ int s_idx;
    if (threadIdx.x == 0) {
        float bv = swv[0]; int bi = swi[0];
#pragma unroll
        for (int w = 1; w < 8; w++)
            if (swv[w] > bv || (swv[w] == bv && swi[w] < bi)) { bv = swv[w]; bi = swi[w]; }
        s_idx = bi;
        g_cntA[b] = 0;  // reset for next graph replay
    }
    __syncthreads();
    const int idx = s_idx;
    const float rn = g_meta[b * NT + idx].x;
    const float* qt = x + ((size_t)b * NT + idx) * NF;
    for (int f = threadIdx.x; f < NF; f += 256)
        g_q[b * NF + f] = qt[f] * rn;
}

// ---------------------------------------------------------------------------
// Kernel C: streaming scoring pass. grid = (NS, NB), 256 threads.
// Per token: ONE dot product s = q.tok (warp-reduced), u = exp(s*rn)*p1,
// then scalar FMAs into (U, D0, D1) using the pre-projections from kA.
// No per-feature accumulator -> low registers -> high occupancy.
// Last-finishing block of the grid reduces all splits and writes output.
// ---------------------------------------------------------------------------
__global__ __launch_bounds__(256) void kC(const float* __restrict__ x,
                                          const float* __restrict__ fc_final_b,
                                          float* __restrict__ out) {
    const int b    = blockIdx.y;
    const int sp   = blockIdx.x;
    const int warp = threadIdx.x >> 5;
    const int lane = threadIdx.x & 31;

    __shared__ float4 q4s[NF / 4];     // 3 KB
    __shared__ float  s0[8], s1[8], su[8];

    const float4* q4 = reinterpret_cast<const float4*>(g_q + b * NF);
    for (int i = threadIdx.x; i < NF / 4; i += 256) q4s[i] = q4[i];
    __syncthreads();

    float U = 0.f, D0 = 0.f, D1 = 0.f;

    const int t0 = sp * TOK_PER_BLK + warp * TOK_PER_WARP;
#pragma unroll
    for (int tt = 0; tt < TOK_PER_WARP; tt++) {
        const int t = t0 + tt;
        const float4 m = g_meta[b * NT + t];   // {rnorm, p1, dw0, dw1}
        const float4* tok = reinterpret_cast<const float4*>(x + ((size_t)b * NT + t) * NF);
        float s = 0.f;
#pragma unroll
        for (int i = 0; i < 6; i++) {
            float4 v = tok[lane + 32 * i];
            float4 q = q4s[lane + 32 * i];
            s += v.x * q.x + v.y * q.y + v.z * q.z + v.w * q.w;
        }
#pragma unroll
        for (int o = 16; o; o >>= 1) s += __shfl_xor_sync(0xffffffffu, s, o);
        const float u = expf(s * m.x) * m.y;   // lane-replicated
        U  += u;
        D0 += u * m.z;
        D1 += u * m.w;
    }

    // U/D0/D1 are lane-replicated: take lane 0's values only (no shuffle!).
    if (lane == 0) { s0[warp] = D0; s1[warp] = D1; su[warp] = U; }
    __syncthreads();

    __shared__ unsigned s_last;
    if (threadIdx.x == 0) {
        float A0 = 0.f, A1 = 0.f, AU = 0.f;
#pragma unroll
        for (int w = 0; w < 8; w++) { A0 += s0[w]; A1 += s1[w]; AU += su[w]; }
        g_d0[b * NS + sp] = A0;
        g_d1[b * NS + sp] = A1;
        g_u [b * NS + sp] = AU;
        __threadfence();
        s_last = atomicAdd(&g_cntC, 1u);
    }
    __syncthreads();
    if (s_last != (unsigned)(NB * NS - 1)) return;
    __threadfence();  // acquire all blocks' partials

    // Final reduce: threads 0..31 each own one batch; fixed summation order.
    if (threadIdx.x < NB) {
        const int bb = threadIdx.x;
        float A0 = 0.f, A1 = 0.f, AU = 0.f;
#pragma unroll
        for (int s = 0; s < NS; s++) {
            A0 += g_d0[bb * NS + s];
            A1 += g_d1[bb * NS + s];
            AU += g_u [bb * NS + s];
        }
        const float invU = 1.f / AU;
        out[bb * 2 + 0] = A0 * invU + fc_final_b[0];
        out[bb * 2 + 1] = A1 * invU + fc_final_b[1];
    }
    if (threadIdx.x == 0) g_cntC = 0;  // reset for next replay
}

// ---------------------------------------------------------------------------
extern "C" void kernel_launch(void* const* d_in, const int* in_sizes, int n_in,
                              void* d_out, int out_size) {
    const float* x          = (const float*)d_in[0];
    const float* fc_w       = (const float*)d_in[1];
    const float* fc_b       = (const float*)d_in[2];
    const float* fc_final_w = (const float*)d_in[3];
    const float* fc_final_b = (const float*)d_in[4];
    float* out = (float*)d_out;

    kA<<<NB * NT / 8, 256>>>(x, fc_w, fc_b, fc_final_w);
    dim3 gridC(NS, NB);
    kC<<<gridC, 256>>>(x, fc_final_b, out);
}

// round 13
// speedup vs baseline: 1.0898x; 1.0898x over previous
#include <cuda_runtime.h>

// Problem constants
constexpr int NB = 32;    // batch
constexpr int NT = 1024;  // tokens (32x32)
constexpr int NF = 768;   // features
constexpr int NS = 32;    // splits per batch in pass C
constexpr int TOK_PER_BLK  = NT / NS;       // 32 tokens per kC block
constexpr int TOK_PER_WARP = TOK_PER_BLK/8; // 4 tokens per warp
constexpr int BLK_PER_BATCH_A = NT / 32;    // 32 kA blocks per batch (1024 thr)

// Scratch (device globals — no allocations; counters self-reset per launch)
__device__ float4 g_meta[NB * NT];   // {rnorm, p1, tok.fw0, tok.fw1}
__device__ float  g_q[NB * NF];      // normalized argmax token per batch
__device__ float  g_d0[NB * NS];
__device__ float  g_d1[NB * NS];
__device__ float  g_u [NB * NS];
__device__ unsigned g_cntA[NB];
__device__ unsigned g_cntC;

// ---------------------------------------------------------------------------
// Kernel A: 1024 threads, one warp per token (32 tokens/block). Computes
// ||tok||, tok.(w0-w1) (-> p1 via sigmoid) and tok.fc_final_w{0,1}.
// Weight streams reduced to 3 via wd = w0-w1. Last-finishing block per batch
// does the argmax (first-max tiebreak, matches jnp.argmax) and writes
// q = tok[idx]*rnorm.
// ---------------------------------------------------------------------------
__global__ __launch_bounds__(1024) void kA(const float* __restrict__ x,
                                           const float* __restrict__ fc_w,
                                           const float* __restrict__ fc_b,
                                           const float* __restrict__ fc_final_w) {
    const int warp = threadIdx.x >> 5;
    const int lane = threadIdx.x & 31;
    const int g = blockIdx.x * 32 + warp;         // global token id
    const int b = blockIdx.x / BLK_PER_BATCH_A;   // batch of this block

    __shared__ float ws[3 * NF];                  // 9 KB: wd, fw0, fw1
    for (int i = threadIdx.x; i < NF; i += 1024)
        ws[i] = fc_w[i] - fc_w[NF + i];           // wd = w0 - w1
    for (int i = threadIdx.x; i < 2 * NF; i += 1024)
        ws[NF + i] = fc_final_w[i];
    __syncthreads();
    const float4* wd = reinterpret_cast<const float4*>(ws);
    const float4* f0 = reinterpret_cast<const float4*>(ws + NF);
    const float4* f1 = reinterpret_cast<const float4*>(ws + 2 * NF);

    const float4* tok = reinterpret_cast<const float4*>(x + (size_t)g * NF);

    float nrm = 0.f, d = 0.f, e0 = 0.f, e1 = 0.f;
#pragma unroll
    for (int i = 0; i < 6; i++) {
        float4 v = tok[lane + 32 * i];
        float4 a = wd[lane + 32 * i];
        float4 p = f0[lane + 32 * i];
        float4 q = f1[lane + 32 * i];
        nrm += v.x * v.x + v.y * v.y + v.z * v.z + v.w * v.w;
        d   += v.x * a.x + v.y * a.y + v.z * a.z + v.w * a.w;
        e0  += v.x * p.x + v.y * p.y + v.z * p.z + v.w * p.w;
        e1  += v.x * q.x + v.y * q.y + v.z * q.z + v.w * q.w;
    }
#pragma unroll
    for (int o = 16; o; o >>= 1) {
        nrm += __shfl_xor_sync(0xffffffffu, nrm, o);
        d   += __shfl_xor_sync(0xffffffffu, d, o);
        e0  += __shfl_xor_sync(0xffffffffu, e0, o);
        e1  += __shfl_xor_sync(0xffffffffu, e1, o);
    }
    if (lane == 0) {
        const float bd = fc_b[0] - fc_b[1];
        const float p1 = 1.f / (1.f + expf(d + bd));   // = softmax[1]
        g_meta[g] = make_float4(rsqrtf(nrm), p1, e0, e1);
    }
    __syncthreads();

    // Single release fence per block (syncthreads orders all block writes
    // before thread 0's gpu-scope fence + atomic).
    __shared__ unsigned s_last;
    if (threadIdx.x == 0) {
        __threadfence();
        s_last = atomicAdd(&g_cntA[b], 1u);
    }
    __syncthreads();
    if (s_last != BLK_PER_BATCH_A - 1) return;
    __threadfence();  // acquire: see all blocks' meta writes

    // argmax over 1024 p1 values: exactly one candidate per thread.
    // Comparator (v>best)||(v==best && i<besti) => global first-max.
    float bestv = g_meta[b * NT + threadIdx.x].y;
    int   besti = threadIdx.x;
#pragma unroll
    for (int o = 16; o; o >>= 1) {
        float v2 = __shfl_xor_sync(0xffffffffu, bestv, o);
        int   i2 = __shfl_xor_sync(0xffffffffu, besti, o);
        if (v2 > bestv || (v2 == bestv && i2 < besti)) { bestv = v2; besti = i2; }
    }
    __shared__ float swv[32];
    __shared__ int   swi[32];
    if (lane == 0) { swv[warp] = bestv; swi[warp] = besti; }
    __syncthreads();
    __shared__ int s_idx;
    if (warp == 0) {
        bestv = swv[lane]; besti = swi[lane];
#pragma unroll
        for (int o = 16; o; o >>= 1) {
            float v2 = __shfl_xor_sync(0xffffffffu, bestv, o);
            int   i2 = __shfl_xor_sync(0xffffffffu, besti, o);
            if (v2 > bestv || (v2 == bestv && i2 < besti)) { bestv = v2; besti = i2; }
        }
        if (lane == 0) {
            s_idx = besti;
            g_cntA[b] = 0;  // reset for next graph replay
        }
    }
    __syncthreads();
    const int idx = s_idx;
    const float rn = g_meta[b * NT + idx].x;
    const float* qt = x + ((size_t)b * NT + idx) * NF;
    if (threadIdx.x < NF)
        g_q[b * NF + threadIdx.x] = qt[threadIdx.x] * rn;
}

// ---------------------------------------------------------------------------
// Kernel C: streaming scoring pass. grid = (NS, NB), 256 threads, warp per
// token x4. Explicit double-buffered pipeline: loads for token tt+1 are
// issued BEFORE the shuffle-reduce/exp chain of token tt, keeping >=6 loads
// in flight per warp at all times. Metas prefetched up front.
// Last-finishing block of the grid reduces all splits and writes output.
// ---------------------------------------------------------------------------
__global__ __launch_bounds__(256) void kC(const float* __restrict__ x,
                                          const float* __restrict__ fc_final_b,
                                          float* __restrict__ out) {
    const int b    = blockIdx.y;
    const int sp   = blockIdx.x;
    const int warp = threadIdx.x >> 5;
    const int lane = threadIdx.x & 31;

    __shared__ float4 q4s[NF / 4];     // 3 KB
    __shared__ float  s0[8], s1[8], su[8];

    const float4* q4 = reinterpret_cast<const float4*>(g_q + b * NF);
    for (int i = threadIdx.x; i < NF / 4; i += 256) q4s[i] = q4[i];
    __syncthreads();

    const int t0 = sp * TOK_PER_BLK + warp * TOK_PER_WARP;

    // Prefetch all 4 metas (independent broadcast loads)
    float4 m[TOK_PER_WARP];
#pragma unroll
    for (int tt = 0; tt < TOK_PER_WARP; tt++)
        m[tt] = g_meta[b * NT + t0 + tt];

    const float4* base = reinterpret_cast<const float4*>(x + (size_t)b * NT * NF);

    float U = 0.f, D0 = 0.f, D1 = 0.f;
    float4 buf[2][6];

    // Prologue: load token t0 into buf[0]
#pragma unroll
    for (int i = 0; i < 6; i++)
        buf[0][i] = base[(size_t)t0 * (NF / 4) + lane + 32 * i];

#pragma unroll
    for (int tt = 0; tt < TOK_PER_WARP; tt++) {
        const int cur = tt & 1, nxt = cur ^ 1;
        // Issue next token's loads FIRST (in flight during reduce/exp below)
        if (tt < TOK_PER_WARP - 1) {
#pragma unroll
            for (int i = 0; i < 6; i++)
                buf[nxt][i] = base[(size_t)(t0 + tt + 1) * (NF / 4) + lane + 32 * i];
        }
        float s = 0.f;
#pragma unroll
        for (int i = 0; i < 6; i++) {
            float4 v = buf[cur][i];
            float4 q = q4s[lane + 32 * i];
            s += v.x * q.x + v.y * q.y + v.z * q.z + v.w * q.w;
        }
#pragma unroll
        for (int o = 16; o; o >>= 1) s += __shfl_xor_sync(0xffffffffu, s, o);
        const float u = expf(s * m[tt].x) * m[tt].y;   // lane-replicated
        U  += u;
        D0 += u * m[tt].z;
        D1 += u * m[tt].w;
    }

    // U/D0/D1 are lane-replicated: take lane 0's values only (no shuffle!).
    if (lane == 0) { s0[warp] = D0; s1[warp] = D1; su[warp] = U; }
    __syncthreads();

    __shared__ unsigned s_last;
    if (threadIdx.x == 0) {
        float A0 = 0.f, A1 = 0.f, AU = 0.f;
#pragma unroll
        for (int w = 0; w < 8; w++) { A0 += s0[w]; A1 += s1[w]; AU += su[w]; }
        g_d0[b * NS + sp] = A0;
        g_d1[b * NS + sp] = A1;
        g_u [b * NS + sp] = AU;
        __threadfence();
        s_last = atomicAdd(&g_cntC, 1u);
    }
    __syncthreads();
    if (s_last != (unsigned)(NB * NS - 1)) return;
    __threadfence();  // acquire all blocks' partials

    // Final reduce: threads 0..31 each own one batch; fixed summation order.
    if (threadIdx.x < NB) {
        const int bb = threadIdx.x;
        float A0 = 0.f, A1 = 0.f, AU = 0.f;
#pragma unroll
        for (int s = 0; s < NS; s++) {
            A0 += g_d0[bb * NS + s];
            A1 += g_d1[bb * NS + s];
            AU += g_u [bb * NS + s];
        }
        const float invU = 1.f / AU;
        out[bb * 2 + 0] = A0 * invU + fc_final_b[0];
        out[bb * 2 + 1] = A1 * invU + fc_final_b[1];
    }
    if (threadIdx.x == 0) g_cntC = 0;  // reset for next replay
}

// ---------------------------------------------------------------------------
extern "C" void kernel_launch(void* const* d_in, const int* in_sizes, int n_in,
                              void* d_out, int out_size) {
    const float* x          = (const float*)d_in[0];
    const float* fc_w       = (const float*)d_in[1];
    const float* fc_b       = (const float*)d_in[2];
    const float* fc_final_w = (const float*)d_in[3];
    const float* fc_final_b = (const float*)d_in[4];
    float* out = (float*)d_out;

    kA<<<NB * NT / 32, 1024>>>(x, fc_w, fc_b, fc_final_w);
    dim3 gridC(NS, NB);
    kC<<<gridC, 256>>>(x, fc_final_b, out);
}

// round 14
// speedup vs baseline: 1.1069x; 1.0157x over previous
#include <cuda_runtime.h>

// Problem constants
constexpr int NB = 32;    // batch
constexpr int NT = 1024;  // tokens (32x32)
constexpr int NF = 768;   // features
constexpr int NS = 32;    // splits per batch in pass C
constexpr int TOK_PER_BLK  = NT / NS;       // 32 tokens per kC block
constexpr int TOK_PER_WARP = TOK_PER_BLK/8; // 4 tokens per warp
constexpr int BLK_PER_BATCH_A = NT / 32;    // 32 kA blocks per batch (1024 thr)

// Scratch (device globals — no allocations; counters self-reset per launch)
__device__ float4 g_meta[NB * NT];   // {rnorm, p1, tok.fw0, tok.fw1}
__device__ float  g_q[NB * NF];      // normalized argmax token per batch
__device__ float  g_d0[NB * NS];
__device__ float  g_d1[NB * NS];
__device__ float  g_u [NB * NS];
__device__ unsigned g_cntA[NB];
__device__ unsigned g_cntC;

// ---------------------------------------------------------------------------
// Kernel A: 1024 threads, one warp per token (32 tokens/block). Computes
// ||tok||, tok.(w0-w1) (-> p1 via sigmoid) and tok.fc_final_w{0,1}.
// Weight streams reduced to 3 via wd = w0-w1. Last-finishing block per batch
// does the argmax (first-max tiebreak, matches jnp.argmax) and writes
// q = tok[idx]*rnorm.
// ---------------------------------------------------------------------------
__global__ __launch_bounds__(1024) void kA(const float* __restrict__ x,
                                           const float* __restrict__ fc_w,
                                           const float* __restrict__ fc_b,
                                           const float* __restrict__ fc_final_w) {
    const int warp = threadIdx.x >> 5;
    const int lane = threadIdx.x & 31;
    const int g = blockIdx.x * 32 + warp;         // global token id
    const int b = blockIdx.x / BLK_PER_BATCH_A;   // batch of this block

    __shared__ float ws[3 * NF];                  // 9 KB: wd, fw0, fw1
    for (int i = threadIdx.x; i < NF; i += 1024)
        ws[i] = fc_w[i] - fc_w[NF + i];           // wd = w0 - w1
    for (int i = threadIdx.x; i < 2 * NF; i += 1024)
        ws[NF + i] = fc_final_w[i];
    __syncthreads();
    const float4* wd = reinterpret_cast<const float4*>(ws);
    const float4* f0 = reinterpret_cast<const float4*>(ws + NF);
    const float4* f1 = reinterpret_cast<const float4*>(ws + 2 * NF);

    const float4* tok = reinterpret_cast<const float4*>(x + (size_t)g * NF);

    float nrm = 0.f, d = 0.f, e0 = 0.f, e1 = 0.f;
#pragma unroll
    for (int i = 0; i < 6; i++) {
        float4 v = tok[lane + 32 * i];
        float4 a = wd[lane + 32 * i];
        float4 p = f0[lane + 32 * i];
        float4 q = f1[lane + 32 * i];
        nrm += v.x * v.x + v.y * v.y + v.z * v.z + v.w * v.w;
        d   += v.x * a.x + v.y * a.y + v.z * a.z + v.w * a.w;
        e0  += v.x * p.x + v.y * p.y + v.z * p.z + v.w * p.w;
        e1  += v.x * q.x + v.y * q.y + v.z * q.z + v.w * q.w;
    }
#pragma unroll
    for (int o = 16; o; o >>= 1) {
        nrm += __shfl_xor_sync(0xffffffffu, nrm, o);
        d   += __shfl_xor_sync(0xffffffffu, d, o);
        e0  += __shfl_xor_sync(0xffffffffu, e0, o);
        e1  += __shfl_xor_sync(0xffffffffu, e1, o);
    }
    if (lane == 0) {
        const float bd = fc_b[0] - fc_b[1];
        const float p1 = 1.f / (1.f + expf(d + bd));   // = softmax[1]
        g_meta[g] = make_float4(rsqrtf(nrm), p1, e0, e1);
    }
    __syncthreads();

    // Single release fence per block (syncthreads orders all block writes
    // before thread 0's gpu-scope fence + atomic).
    __shared__ unsigned s_last;
    if (threadIdx.x == 0) {
        __threadfence();
        s_last = atomicAdd(&g_cntA[b], 1u);
    }
    __syncthreads();
    if (s_last != BLK_PER_BATCH_A - 1) return;
    __threadfence();  // acquire: see all blocks' meta writes

    // argmax over 1024 p1 values: exactly one candidate per thread.
    // Comparator (v>best)||(v==best && i<besti) => global first-max.
    float bestv = g_meta[b * NT + threadIdx.x].y;
    int   besti = threadIdx.x;
#pragma unroll
    for (int o = 16; o; o >>= 1) {
        float v2 = __shfl_xor_sync(0xffffffffu, bestv, o);
        int   i2 = __shfl_xor_sync(0xffffffffu, besti, o);
        if (v2 > bestv || (v2 == bestv && i2 < besti)) { bestv = v2; besti = i2; }
    }
    __shared__ float swv[32];
    __shared__ int   swi[32];
    if (lane == 0) { swv[warp] = bestv; swi[warp] = besti; }
    __syncthreads();
    __shared__ int s_idx;
    if (warp == 0) {
        bestv = swv[lane]; besti = swi[lane];
#pragma unroll
        for (int o = 16; o; o >>= 1) {
            float v2 = __shfl_xor_sync(0xffffffffu, bestv, o);
            int   i2 = __shfl_xor_sync(0xffffffffu, besti, o);
            if (v2 > bestv || (v2 == bestv && i2 < besti)) { bestv = v2; besti = i2; }
        }
        if (lane == 0) {
            s_idx = besti;
            g_cntA[b] = 0;  // reset for next graph replay
        }
    }
    __syncthreads();
    const int idx = s_idx;
    const float rn = g_meta[b * NT + idx].x;
    const float* qt = x + ((size_t)b * NT + idx) * NF;
    if (threadIdx.x < NF)
        g_q[b * NF + threadIdx.x] = qt[threadIdx.x] * rn;
}

// ---------------------------------------------------------------------------
// Kernel C: streaming scoring pass. grid = (NS, NB), 256 threads, warp per
// token x4. Explicit double-buffered pipeline: loads for token tt+1 are
// issued BEFORE the shuffle-reduce/exp chain of token tt, keeping >=6 loads
// in flight per warp at all times. Metas prefetched up front.
// Last-finishing block of the grid reduces all splits and writes output.
// ---------------------------------------------------------------------------
__global__ __launch_bounds__(256) void kC(const float* __restrict__ x,
                                          const float* __restrict__ fc_final_b,
                                          float* __restrict__ out) {
    const int b    = blockIdx.y;
    const int sp   = blockIdx.x;
    const int warp = threadIdx.x >> 5;
    const int lane = threadIdx.x & 31;

    __shared__ float4 q4s[NF / 4];     // 3 KB
    __shared__ float  s0[8], s1[8], su[8];

    const float4* q4 = reinterpret_cast<const float4*>(g_q + b * NF);
    for (int i = threadIdx.x; i < NF / 4; i += 256) q4s[i] = q4[i];
    __syncthreads();

    const int t0 = sp * TOK_PER_BLK + warp * TOK_PER_WARP;

    // Prefetch all 4 metas (independent broadcast loads)
    float4 m[TOK_PER_WARP];
#pragma unroll
    for (int tt = 0; tt < TOK_PER_WARP; tt++)
        m[tt] = g_meta[b * NT + t0 + tt];

    const float4* base = reinterpret_cast<const float4*>(x + (size_t)b * NT * NF);

    float U = 0.f, D0 = 0.f, D1 = 0.f;
    float4 buf[2][6];

    // Prologue: load token t0 into buf[0]
#pragma unroll
    for (int i = 0; i < 6; i++)
        buf[0][i] = base[(size_t)t0 * (NF / 4) + lane + 32 * i];

#pragma unroll
    for (int tt = 0; tt < TOK_PER_WARP; tt++) {
        const int cur = tt & 1, nxt = cur ^ 1;
        // Issue next token's loads FIRST (in flight during reduce/exp below)
        if (tt < TOK_PER_WARP - 1) {
#pragma unroll
            for (int i = 0; i < 6; i++)
                buf[nxt][i] = base[(size_t)(t0 + tt + 1) * (NF / 4) + lane + 32 * i];
        }
        float s = 0.f;
#pragma unroll
        for (int i = 0; i < 6; i++) {
            float4 v = buf[cur][i];
            float4 q = q4s[lane + 32 * i];
            s += v.x * q.x + v.y * q.y + v.z * q.z + v.w * q.w;
        }
#pragma unroll
        for (int o = 16; o; o >>= 1) s += __shfl_xor_sync(0xffffffffu, s, o);
        const float u = expf(s * m[tt].x) * m[tt].y;   // lane-replicated
        U  += u;
        D0 += u * m[tt].z;
        D1 += u * m[tt].w;
    }

    // U/D0/D1 are lane-replicated: take lane 0's values only (no shuffle!).
    if (lane == 0) { s0[warp] = D0; s1[warp] = D1; su[warp] = U; }
    __syncthreads();

    __shared__ unsigned s_last;
    if (threadIdx.x == 0) {
        float A0 = 0.f, A1 = 0.f, AU = 0.f;
#pragma unroll
        for (int w = 0; w < 8; w++) { A0 += s0[w]; A1 += s1[w]; AU += su[w]; }
        g_d0[b * NS + sp] = A0;
        g_d1[b * NS + sp] = A1;
        g_u [b * NS + sp] = AU;
        __threadfence();
        s_last = atomicAdd(&g_cntC, 1u);
    }
    __syncthreads();
    if (s_last != (unsigned)(NB * NS - 1)) return;
    __threadfence();  // acquire all blocks' partials

    // Final reduce: threads 0..31 each own one batch; fixed summation order.
    if (threadIdx.x < NB) {
        const int bb = threadIdx.x;
        float A0 = 0.f, A1 = 0.f, AU = 0.f;
#pragma unroll
        for (int s = 0; s < NS; s++) {
            A0 += g_d0[bb * NS + s];
            A1 += g_d1[bb * NS + s];
            AU += g_u [bb * NS + s];
        }
        const float invU = 1.f / AU;
        out[bb * 2 + 0] = A0 * invU + fc_final_b[0];
        out[bb * 2 + 1] = A1 * invU + fc_final_b[1];
    }
    if (threadIdx.x == 0) g_cntC = 0;  // reset for next replay
}

// ---------------------------------------------------------------------------
extern "C" void kernel_launch(void* const* d_in, const int* in_sizes, int n_in,
                              void* d_out, int out_size) {
    const float* x          = (const float*)d_in[0];
    const float* fc_w       = (const float*)d_in[1];
    const float* fc_b       = (const float*)d_in[2];
    const float* fc_final_w = (const float*)d_in[3];
    const float* fc_final_b = (const float*)d_in[4];
    float* out = (float*)d_out;

    kA<<<NB * NT / 32, 1024>>>(x, fc_w, fc_b, fc_final_w);
    dim3 gridC(NS, NB);
    kC<<<gridC, 256>>>(x, fc_final_b, out);
}

// round 15
// speedup vs baseline: 1.4182x; 1.2812x over previous
#include <cuda_runtime.h>

// Problem constants
constexpr int NB = 32;    // batch
constexpr int NT = 1024;  // tokens (32x32)
constexpr int NF = 768;   // features
constexpr int NC = NF / 128;                // 6 feature chunks of 128 (32 lanes x float4)
constexpr int NS = 32;    // splits per batch in pass C
constexpr int TPW = 4;    // tokens per warp (processed simultaneously)
constexpr int TOK_PER_BLK_C = NT / NS;      // 32 tokens per kC block (8 warps x 4)
constexpr int BLK_PER_BATCH_A = NT / 32;    // 32 kA blocks per batch (8 warps x 4 tok)

// Scratch (device globals — no allocations; counters self-reset per launch)
__device__ float4 g_meta[NB * NT];   // {rnorm, p1, tok.fw0, tok.fw1}
__device__ float  g_q[NB * NF];      // normalized argmax token per batch
__device__ float  g_d0[NB * NS];
__device__ float  g_d1[NB * NS];
__device__ float  g_u [NB * NS];
__device__ unsigned g_cntA[NB];
__device__ unsigned g_cntC;

__device__ __forceinline__ float dot4(float4 a, float4 b) {
    return a.x * b.x + a.y * b.y + a.z * b.z + a.w * b.w;
}

// ---------------------------------------------------------------------------
// Kernel A: 256 threads, each warp processes 4 tokens SIMULTANEOUSLY
// (chunk-major loop -> 4 independent global loads in flight per step, smem
// weight reads amortized over 4 tokens). Computes ||tok||, tok.(w0-w1)
// (-> p1) and tok.fc_final_w{0,1}, packed into one float4 per token.
// Last-finishing block per batch does the argmax (first-max tiebreak,
// matches jnp.argmax) and writes q = tok[idx]*rnorm.
// ---------------------------------------------------------------------------
__global__ __launch_bounds__(256) void kA(const float* __restrict__ x,
                                          const float* __restrict__ fc_w,
                                          const float* __restrict__ fc_b,
                                          const float* __restrict__ fc_final_w) {
    const int warp = threadIdx.x >> 5;
    const int lane = threadIdx.x & 31;
    const int g0 = blockIdx.x * 32 + warp * TPW; // first token of this warp
    const int b  = blockIdx.x / BLK_PER_BATCH_A; // batch of this block

    __shared__ float ws[3 * NF];                 // 9 KB: wd, fw0, fw1
    for (int i = threadIdx.x; i < NF; i += 256)
        ws[i] = fc_w[i] - fc_w[NF + i];          // wd = w0 - w1
    for (int i = threadIdx.x; i < 2 * NF; i += 256)
        ws[NF + i] = fc_final_w[i];
    __syncthreads();
    const float4* wd = reinterpret_cast<const float4*>(ws);
    const float4* f0 = reinterpret_cast<const float4*>(ws + NF);
    const float4* f1 = reinterpret_cast<const float4*>(ws + 2 * NF);

    const float4* tok0 = reinterpret_cast<const float4*>(x + (size_t)g0 * NF);

    float nrm[TPW], d[TPW], e0[TPW], e1[TPW];
#pragma unroll
    for (int tt = 0; tt < TPW; tt++) { nrm[tt] = d[tt] = e0[tt] = e1[tt] = 0.f; }

#pragma unroll
    for (int i = 0; i < NC; i++) {
        const float4 a = wd[lane + 32 * i];
        const float4 p = f0[lane + 32 * i];
        const float4 q = f1[lane + 32 * i];
#pragma unroll
        for (int tt = 0; tt < TPW; tt++) {
            const float4 v = tok0[(size_t)tt * (NF / 4) + lane + 32 * i];
            nrm[tt] += dot4(v, v);
            d[tt]   += dot4(v, a);
            e0[tt]  += dot4(v, p);
            e1[tt]  += dot4(v, q);
        }
    }
    // 16 independent butterflies, pipelined
#pragma unroll
    for (int o = 16; o; o >>= 1) {
#pragma unroll
        for (int tt = 0; tt < TPW; tt++) {
            nrm[tt] += __shfl_xor_sync(0xffffffffu, nrm[tt], o);
            d[tt]   += __shfl_xor_sync(0xffffffffu, d[tt], o);
            e0[tt]  += __shfl_xor_sync(0xffffffffu, e0[tt], o);
            e1[tt]  += __shfl_xor_sync(0xffffffffu, e1[tt], o);
        }
    }
    if (lane == 0) {
        const float bd = fc_b[0] - fc_b[1];
#pragma unroll
        for (int tt = 0; tt < TPW; tt++) {
            const float p1 = 1.f / (1.f + expf(d[tt] + bd));
            g_meta[g0 + tt] = make_float4(rsqrtf(nrm[tt]), p1, e0[tt], e1[tt]);
        }
    }
    __syncthreads();

    // Single release fence per block (syncthreads orders all block writes
    // before thread 0's gpu-scope fence + atomic).
    __shared__ unsigned s_last;
    if (threadIdx.x == 0) {
        __threadfence();
        s_last = atomicAdd(&g_cntA[b], 1u);
    }
    __syncthreads();
    if (s_last != BLK_PER_BATCH_A - 1) return;
    __threadfence();  // acquire: see all blocks' meta writes

    // argmax over 1024 p1 values, 256 threads x 4 candidates.
    // Comparator (v>best)||(v==best && i<besti) => global first-max.
    float bestv = -1.f; int besti = 0;
#pragma unroll
    for (int k = 0; k < 4; k++) {
        const int t = threadIdx.x + 256 * k;
        const float v = g_meta[b * NT + t].y;
        if (v > bestv || (v == bestv && t < besti)) { bestv = v; besti = t; }
    }
#pragma unroll
    for (int o = 16; o; o >>= 1) {
        float v2 = __shfl_xor_sync(0xffffffffu, bestv, o);
        int   i2 = __shfl_xor_sync(0xffffffffu, besti, o);
        if (v2 > bestv || (v2 == bestv && i2 < besti)) { bestv = v2; besti = i2; }
    }
    __shared__ float swv[8];
    __shared__ int   swi[8];
    if (lane == 0) { swv[warp] = bestv; swi[warp] = besti; }
    __syncthreads();
    __shared__ int s_idx;
    if (threadIdx.x == 0) {
        float bv = swv[0]; int bi = swi[0];
#pragma unroll
        for (int w = 1; w < 8; w++)
            if (swv[w] > bv || (swv[w] == bv && swi[w] < bi)) { bv = swv[w]; bi = swi[w]; }
        s_idx = bi;
        g_cntA[b] = 0;  // reset for next graph replay
    }
    __syncthreads();
    const int idx = s_idx;
    const float rn = g_meta[b * NT + idx].x;
    const float* qt = x + ((size_t)b * NT + idx) * NF;
    for (int f = threadIdx.x; f < NF; f += 256)
        g_q[b * NF + f] = qt[f] * rn;
}

// ---------------------------------------------------------------------------
// Kernel C: streaming scoring pass. grid = (NS, NB), 256 threads. Each warp
// processes 4 tokens SIMULTANEOUSLY (chunk-major): 4 independent loads per
// chunk step keep ~24 loads in flight; the butterfly/exp tail is batched
// over 4 tokens (independent ops, issue-limited not latency-limited).
// Last-finishing block of the grid reduces all splits and writes output.
// ---------------------------------------------------------------------------
__global__ __launch_bounds__(256) void kC(const float* __restrict__ x,
                                          const float* __restrict__ fc_final_b,
                                          float* __restrict__ out) {
    const int b    = blockIdx.y;
    const int sp   = blockIdx.x;
    const int warp = threadIdx.x >> 5;
    const int lane = threadIdx.x & 31;

    __shared__ float4 q4s[NF / 4];     // 3 KB
    __shared__ float  s0[8], s1[8], su[8];

    const float4* q4 = reinterpret_cast<const float4*>(g_q + b * NF);
    for (int i = threadIdx.x; i < NF / 4; i += 256) q4s[i] = q4[i];
    __syncthreads();

    const int t0 = sp * TOK_PER_BLK_C + warp * TPW;

    // Prefetch 4 metas (independent broadcast loads)
    float4 m[TPW];
#pragma unroll
    for (int tt = 0; tt < TPW; tt++)
        m[tt] = g_meta[b * NT + t0 + tt];

    const float4* tok0 = reinterpret_cast<const float4*>(x + ((size_t)b * NT + t0) * NF);

    float s[TPW];
#pragma unroll
    for (int tt = 0; tt < TPW; tt++) s[tt] = 0.f;

#pragma unroll
    for (int i = 0; i < NC; i++) {
        const float4 q = q4s[lane + 32 * i];
#pragma unroll
        for (int tt = 0; tt < TPW; tt++) {
            const float4 v = tok0[(size_t)tt * (NF / 4) + lane + 32 * i];
            s[tt] += dot4(v, q);
        }
    }
    // 4 independent butterflies
#pragma unroll
    for (int o = 16; o; o >>= 1) {
#pragma unroll
        for (int tt = 0; tt < TPW; tt++)
            s[tt] += __shfl_xor_sync(0xffffffffu, s[tt], o);
    }
    float U = 0.f, D0 = 0.f, D1 = 0.f;
#pragma unroll
    for (int tt = 0; tt < TPW; tt++) {
        const float u = expf(s[tt] * m[tt].x) * m[tt].y;  // lane-replicated
        U  += u;
        D0 += u * m[tt].z;
        D1 += u * m[tt].w;
    }

    // U/D0/D1 are lane-replicated: take lane 0's values only (no shuffle!).
    if (lane == 0) { s0[warp] = D0; s1[warp] = D1; su[warp] = U; }
    __syncthreads();

    __shared__ unsigned s_last;
    if (threadIdx.x == 0) {
        float A0 = 0.f, A1 = 0.f, AU = 0.f;
#pragma unroll
        for (int w = 0; w < 8; w++) { A0 += s0[w]; A1 += s1[w]; AU += su[w]; }
        g_d0[b * NS + sp] = A0;
        g_d1[b * NS + sp] = A1;
        g_u [b * NS + sp] = AU;
        __threadfence();
        s_last = atomicAdd(&g_cntC, 1u);
    }
    __syncthreads();
    if (s_last != (unsigned)(NB * NS - 1)) return;
    __threadfence();  // acquire all blocks' partials

    // Final reduce: threads 0..31 each own one batch; fixed summation order.
    if (threadIdx.x < NB) {
        const int bb = threadIdx.x;
        float A0 = 0.f, A1 = 0.f, AU = 0.f;
#pragma unroll
        for (int ss = 0; ss < NS; ss++) {
            A0 += g_d0[bb * NS + ss];
            A1 += g_d1[bb * NS + ss];
            AU += g_u [bb * NS + ss];
        }
        const float invU = 1.f / AU;
        out[bb * 2 + 0] = A0 * invU + fc_final_b[0];
        out[bb * 2 + 1] = A1 * invU + fc_final_b[1];
    }
    if (threadIdx.x == 0) g_cntC = 0;  // reset for next replay
}

// ---------------------------------------------------------------------------
extern "C" void kernel_launch(void* const* d_in, const int* in_sizes, int n_in,
                              void* d_out, int out_size) {
    const float* x          = (const float*)d_in[0];
    const float* fc_w       = (const float*)d_in[1];
    const float* fc_b       = (const float*)d_in[2];
    const float* fc_final_w = (const float*)d_in[3];
    const float* fc_final_b = (const float*)d_in[4];
    float* out = (float*)d_out;

    kA<<<NB * NT / 32, 256>>>(x, fc_w, fc_b, fc_final_w);
    dim3 gridC(NS, NB);
    kC<<<gridC, 256>>>(x, fc_final_b, out);
}